// round 4
// baseline (speedup 1.0000x reference)
#include <cuda_runtime.h>
#include <cstdint>

#define BATCH   4
#define T       1024
#define HPIX    27
#define WPIX    48
#define HW      (HPIX * WPIX)   // 1296
#define NB      512
#define NK4     (NB / 4)        // 128 packed-u8 words per frame
#define LOOK    101
#define PAD     50
#define ODIM    128
#define WSTRIDE 104             // padded win row stride (16B aligned)

// Scratch (device globals; no allocation in kernel_launch per harness rules)
__device__ uint32_t g_histP[BATCH * NK4 * T];       // packed u8 counts, [b][k4][t] (transposed) — 2 MB
__device__ float    g_invn[BATCH * T];              // 1/||hist||
__device__ float    g_win[BATCH * T * WSTRIDE];     // banded sims window — 1.7 MB

// ---------------------------------------------------------------------------
// Kernel 1: per-frame 512-bin color histogram -> packed u8 counts (transposed)
// + inverse L2 norm.
// R4: software-pipelined loads — prefetch next iteration's 3x int4 before
// issuing this iteration's atomics, so 6 LDG.128 are in flight per warp and
// DRAM latency overlaps ATOMS issue.
// ---------------------------------------------------------------------------
#define FPB 4
#define GPF (HW / 4)            // 324 quad-pixel groups per frame
#define NGRP (FPB * GPF)        // 1296
__global__ void __launch_bounds__(256) hist_kernel(const int* __restrict__ frames) {
    __shared__ int sh[FPB * NB];                      // 8 KB
    const int tid = threadIdx.x;
    const int f0  = blockIdx.x * FPB;                 // global frame base

    #pragma unroll
    for (int i = tid; i < FPB * NB; i += 256) sh[i] = 0;
    __syncthreads();

    const int4* base = (const int4*)(frames + (size_t)f0 * HW * 3);

    int  g = tid;
    int4 w0, w1, w2;
    if (g < NGRP) {
        w0 = base[3 * g + 0];
        w1 = base[3 * g + 1];
        w2 = base[3 * g + 2];
    }
    while (g < NGRP) {
        const int gn = g + 256;
        int4 n0, n1, n2;
        if (gn < NGRP) {                // prefetch next iteration
            n0 = base[3 * gn + 0];
            n1 = base[3 * gn + 1];
            n2 = base[3 * gn + 2];
        }
        int* h = sh + (g / GPF) * NB;
        atomicAdd(&h[((w0.x >> 5) << 6) | ((w0.y >> 5) << 3) | (w0.z >> 5)], 1);
        atomicAdd(&h[((w0.w >> 5) << 6) | ((w1.x >> 5) << 3) | (w1.y >> 5)], 1);
        atomicAdd(&h[((w1.z >> 5) << 6) | ((w1.w >> 5) << 3) | (w2.x >> 5)], 1);
        atomicAdd(&h[((w2.y >> 5) << 6) | ((w2.z >> 5) << 3) | (w2.w >> 5)], 1);
        g = gn; w0 = n0; w1 = n1; w2 = n2;
    }
    __syncthreads();

    // inverse norms: warp w handles frame w
    const int lane = tid & 31, w = tid >> 5;
    if (w < FPB) {
        float ss = 0.f;
        #pragma unroll
        for (int k = lane; k < NB; k += 32) {
            float c = (float)sh[w * NB + k];
            ss = fmaf(c, c, ss);
        }
        #pragma unroll
        for (int off = 16; off; off >>= 1) ss += __shfl_xor_sync(0xffffffffu, ss, off);
        if (lane == 0) g_invn[f0 + w] = rsqrtf(ss);   // ss >= 1 always (1296 pixels)
    }

    // pack 4 consecutive bins into u8x4, write k-major (transposed) for band GEMM
    const int b  = f0 >> 10;
    const int t0 = f0 & (T - 1);
    #pragma unroll
    for (int i = tid; i < NK4 * FPB; i += 256) {
        int f  = i & (FPB - 1);
        int k4 = i >> 2;
        int s  = f * NB + k4 * 4;
        uint32_t c0 = min(sh[s + 0], 255), c1 = min(sh[s + 1], 255);
        uint32_t c2 = min(sh[s + 2], 255), c3 = min(sh[s + 3], 255);
        g_histP[(b * NK4 + k4) * T + t0 + f] = c0 | (c1 << 8) | (c2 << 16) | (c3 << 24);
    }
}

// ---------------------------------------------------------------------------
// Kernel 2: banded Gram matrix via exact integer dp4a GEMM.
// R4: double-buffered smem (one __syncthreads per chunk) + global prefetch
// before the dp4a loop — hides load latency at 1-block/SM occupancy.
// ---------------------------------------------------------------------------
#define BK4 16
#define NCH (NK4 / BK4)        // 8 K-chunks
__global__ void __launch_bounds__(256) band_kernel() {
    const int  bb    = blockIdx.y;
    const int  bx    = blockIdx.x;
    const bool super = (bx >= 16);
    const int  it    = super ? bx - 16 : bx;
    const int  t0    = it * 64;
    const int  u0    = super ? t0 + 64 : t0;

    __shared__ uint32_t As[2][BK4][64];
    __shared__ uint32_t Bs[2][BK4][64];
    __shared__ float    sInvT[64], sInvU[64];

    const int tid = threadIdx.x;
    if (tid < 64)       sInvT[tid]      = g_invn[bb * T + t0 + tid];
    else if (tid < 128) sInvU[tid - 64] = g_invn[bb * T + u0 + (tid - 64)];

    const uint32_t* hp = g_histP + bb * NK4 * T;
    const int lk = tid >> 4;           // loader: k row within chunk
    const int lq = (tid & 15) * 4;     // loader: 4-col group
    const int tx = (tid & 15) * 4;     // compute: u micro base
    const int ty = (tid >> 4) * 4;     // compute: t micro base

    unsigned int acc[4][4];
    #pragma unroll
    for (int r = 0; r < 4; r++)
        #pragma unroll
        for (int c = 0; c < 4; c++) acc[r][c] = 0u;

    // preload chunk 0
    {
        const uint32_t* rowp = hp + (size_t)lk * T;
        *(uint4*)&As[0][lk][lq] = *(const uint4*)(rowp + t0 + lq);
        *(uint4*)&Bs[0][lk][lq] = *(const uint4*)(rowp + u0 + lq);
    }
    __syncthreads();

    #pragma unroll
    for (int ch = 0; ch < NCH; ch++) {
        const int cur = ch & 1;
        // prefetch next chunk into the other buffer (issues LDGs before dp4a)
        if (ch + 1 < NCH) {
            const uint32_t* rowp = hp + (size_t)((ch + 1) * BK4 + lk) * T;
            uint4 a  = *(const uint4*)(rowp + t0 + lq);
            uint4 bw = *(const uint4*)(rowp + u0 + lq);
            *(uint4*)&As[cur ^ 1][lk][lq] = a;
            *(uint4*)&Bs[cur ^ 1][lk][lq] = bw;
        }
        #pragma unroll
        for (int k = 0; k < BK4; k++) {
            uint4 av = *(const uint4*)&As[cur][k][ty];
            uint4 bv = *(const uint4*)&Bs[cur][k][tx];
            unsigned int ar[4] = {av.x, av.y, av.z, av.w};
            unsigned int br[4] = {bv.x, bv.y, bv.z, bv.w};
            #pragma unroll
            for (int r = 0; r < 4; r++)
                #pragma unroll
                for (int c = 0; c < 4; c++)
                    acc[r][c] = __dp4a(ar[r], br[c], acc[r][c]);
        }
        __syncthreads();
    }

    // Epilogue: scale by 1/(||t|| ||u||), scatter into the +-50 band window.
    #pragma unroll
    for (int r = 0; r < 4; r++) {
        int   t   = t0 + ty + r;
        float ivt = sInvT[ty + r];
        #pragma unroll
        for (int c = 0; c < 4; c++) {
            int u = u0 + tx + c;
            int d = u - t;
            if (d >= -PAD && d <= PAD) {
                float v = (float)acc[r][c] * ivt * sInvU[tx + c];
                g_win[(bb * T + t) * WSTRIDE + (d + PAD)] = v;
                if (super) g_win[(bb * T + u) * WSTRIDE + (PAD - d)] = v;
            }
        }
    }
}

// ---------------------------------------------------------------------------
// Kernel 3: out = relu(win @ fc_w + fc_b). 32 t-rows per block, 4x4
// micro-tiles, fc_w served from L1 (51.7 KB resident). Window boundary
// entries are zeroed at shared-load time (g_win never initialized there).
// ---------------------------------------------------------------------------
__global__ void __launch_bounds__(256) fc_kernel(const float* __restrict__ fc_w,
                                                 const float* __restrict__ fc_b,
                                                 float* __restrict__ out) {
    const int tid = threadIdx.x;
    const int g0  = blockIdx.x * 32;        // global frame base
    const int t0  = g0 & (T - 1);           // within-batch index

    __shared__ float wins[32][WSTRIDE];
    for (int i = tid; i < 32 * WSTRIDE; i += 256) {
        int r = i / WSTRIDE, l = i - r * WSTRIDE;
        int u = t0 + r + l - PAD;
        float v = 0.f;
        if (l < LOOK && (unsigned)u < (unsigned)T)
            v = g_win[(size_t)(g0 + r) * WSTRIDE + l];
        wins[r][l] = v;
    }
    __syncthreads();

    const int tx = (tid & 31) * 4;          // output-channel base (0..124)
    const int ty = (tid >> 5) * 4;          // t micro base (0..28)

    float4 b4 = *(const float4*)(fc_b + tx);
    float acc[4][4];
    #pragma unroll
    for (int r = 0; r < 4; r++) {
        acc[r][0] = b4.x; acc[r][1] = b4.y; acc[r][2] = b4.z; acc[r][3] = b4.w;
    }

    for (int l = 0; l < LOOK; l++) {
        float4 wv = *(const float4*)(fc_w + l * ODIM + tx);
        float a0 = wins[ty + 0][l];
        float a1 = wins[ty + 1][l];
        float a2 = wins[ty + 2][l];
        float a3 = wins[ty + 3][l];
        acc[0][0] = fmaf(a0, wv.x, acc[0][0]); acc[0][1] = fmaf(a0, wv.y, acc[0][1]);
        acc[0][2] = fmaf(a0, wv.z, acc[0][2]); acc[0][3] = fmaf(a0, wv.w, acc[0][3]);
        acc[1][0] = fmaf(a1, wv.x, acc[1][0]); acc[1][1] = fmaf(a1, wv.y, acc[1][1]);
        acc[1][2] = fmaf(a1, wv.z, acc[1][2]); acc[1][3] = fmaf(a1, wv.w, acc[1][3]);
        acc[2][0] = fmaf(a2, wv.x, acc[2][0]); acc[2][1] = fmaf(a2, wv.y, acc[2][1]);
        acc[2][2] = fmaf(a2, wv.z, acc[2][2]); acc[2][3] = fmaf(a2, wv.w, acc[2][3]);
        acc[3][0] = fmaf(a3, wv.x, acc[3][0]); acc[3][1] = fmaf(a3, wv.y, acc[3][1]);
        acc[3][2] = fmaf(a3, wv.z, acc[3][2]); acc[3][3] = fmaf(a3, wv.w, acc[3][3]);
    }

    #pragma unroll
    for (int r = 0; r < 4; r++) {
        float4 o4;
        o4.x = fmaxf(acc[r][0], 0.f);
        o4.y = fmaxf(acc[r][1], 0.f);
        o4.z = fmaxf(acc[r][2], 0.f);
        o4.w = fmaxf(acc[r][3], 0.f);
        *(float4*)(out + (size_t)(g0 + ty + r) * ODIM + tx) = o4;
    }
}

// ---------------------------------------------------------------------------
extern "C" void kernel_launch(void* const* d_in, const int* in_sizes, int n_in,
                              void* d_out, int out_size) {
    const int*   frames = (const int*)d_in[0];
    const float* fc_w   = (const float*)d_in[1];
    const float* fc_b   = (const float*)d_in[2];
    float*       out    = (float*)d_out;

    hist_kernel<<<(BATCH * T) / FPB, 256>>>(frames);          // 1024 blocks
    band_kernel<<<dim3(31, BATCH), 256>>>();                  // 124 blocks
    fc_kernel<<<(BATCH * T) / 32, 256>>>(fc_w, fc_b, out);    // 128 blocks
}

// round 6
// speedup vs baseline: 1.1501x; 1.1501x over previous
#include <cuda_runtime.h>
#include <cstdint>

#define BATCH   4
#define T       1024
#define HPIX    27
#define WPIX    48
#define HW      (HPIX * WPIX)   // 1296
#define NB      512
#define NK4     (NB / 4)        // 128 packed-u8 words per frame
#define LOOK    101
#define PAD     50
#define ODIM    128
#define WSTRIDE 104             // padded win row stride (16B aligned)
#define NWIN    (BATCH * T * WSTRIDE)

// Scratch (device globals; no allocation in kernel_launch per harness rules)
__device__ uint32_t g_histP[BATCH * NK4 * T];   // packed u8 counts, [b][k4][t] (transposed)
__device__ float    g_invn[BATCH * T];          // 1/||hist||
__device__ uint32_t g_winI[NWIN];               // banded INTEGER dots (atomic-accumulated)

// ---------------------------------------------------------------------------
// Kernel 1: per-frame 512-bin color histogram -> packed u8 counts (transposed)
// + inverse L2 norm. Also zero-fills g_winI for the band kernel's atomic
// accumulation (stream order guarantees completion before band runs).
// ---------------------------------------------------------------------------
#define FPB 4
#define GPF (HW / 4)            // 324 quad-pixel groups per frame
#define NGRP (FPB * GPF)        // 1296
__global__ void __launch_bounds__(256) hist_kernel(const int* __restrict__ frames) {
    __shared__ int sh[FPB * NB];                      // 8 KB
    const int tid = threadIdx.x;
    const int f0  = blockIdx.x * FPB;                 // global frame base

    // zero my slice of g_winI (uint4 stores; NWIN % 4 == 0)
    {
        uint4* wz = (uint4*)g_winI;
        const int nw4 = NWIN / 4;                     // 106496
        for (int i = blockIdx.x * 256 + tid; i < nw4; i += gridDim.x * 256)
            wz[i] = make_uint4(0u, 0u, 0u, 0u);
    }

    #pragma unroll
    for (int i = tid; i < FPB * NB; i += 256) sh[i] = 0;
    __syncthreads();

    const int4* base = (const int4*)(frames + (size_t)f0 * HW * 3);
    int  g = tid;
    int4 w0, w1, w2;
    if (g < NGRP) {
        w0 = base[3 * g + 0];
        w1 = base[3 * g + 1];
        w2 = base[3 * g + 2];
    }
    while (g < NGRP) {
        const int gn = g + 256;
        int4 n0, n1, n2;
        if (gn < NGRP) {                // prefetch next iteration
            n0 = base[3 * gn + 0];
            n1 = base[3 * gn + 1];
            n2 = base[3 * gn + 2];
        }
        int* h = sh + (g / GPF) * NB;
        atomicAdd(&h[((w0.x >> 5) << 6) | ((w0.y >> 5) << 3) | (w0.z >> 5)], 1);
        atomicAdd(&h[((w0.w >> 5) << 6) | ((w1.x >> 5) << 3) | (w1.y >> 5)], 1);
        atomicAdd(&h[((w1.z >> 5) << 6) | ((w1.w >> 5) << 3) | (w2.x >> 5)], 1);
        atomicAdd(&h[((w2.y >> 5) << 6) | ((w2.z >> 5) << 3) | (w2.w >> 5)], 1);
        g = gn; w0 = n0; w1 = n1; w2 = n2;
    }
    __syncthreads();

    // inverse norms: warp w handles frame w
    const int lane = tid & 31, w = tid >> 5;
    if (w < FPB) {
        float ss = 0.f;
        #pragma unroll
        for (int k = lane; k < NB; k += 32) {
            float c = (float)sh[w * NB + k];
            ss = fmaf(c, c, ss);
        }
        #pragma unroll
        for (int off = 16; off; off >>= 1) ss += __shfl_xor_sync(0xffffffffu, ss, off);
        if (lane == 0) g_invn[f0 + w] = rsqrtf(ss);   // ss >= 1 always
    }

    // pack 4 consecutive bins into u8x4, write k-major (transposed)
    const int b  = f0 >> 10;
    const int t0 = f0 & (T - 1);
    #pragma unroll
    for (int i = tid; i < NK4 * FPB; i += 256) {
        int f  = i & (FPB - 1);
        int k4 = i >> 2;
        int s  = f * NB + k4 * 4;
        uint32_t c0 = min(sh[s + 0], 255), c1 = min(sh[s + 1], 255);
        uint32_t c2 = min(sh[s + 2], 255), c3 = min(sh[s + 3], 255);
        g_histP[(b * NK4 + k4) * T + t0 + f] = c0 | (c1 << 8) | (c2 << 16) | (c3 << 24);
    }
}

// ---------------------------------------------------------------------------
// Kernel 2: banded Gram matrix, exact integer dp4a GEMM.
// R5: 2-way K-split (grid.z) -> 248 blocks (2 blocks/SM, 16 warps/SM).
// Each block accumulates its half-K integer partial dot into g_winI via
// atomicAdd (exact, deterministic). Normalization deferred to fc_kernel.
// ---------------------------------------------------------------------------
#define BK4   16
#define KHALF (NK4 / 2)         // 64 words per K-split
#define NCH   (KHALF / BK4)     // 4 chunks
__global__ void __launch_bounds__(256) band_kernel() {
    const int  bb    = blockIdx.y;
    const int  ks    = blockIdx.z;           // K-split index (0/1)
    const int  bx    = blockIdx.x;
    const bool super = (bx >= 16);
    const int  it    = super ? bx - 16 : bx;
    const int  t0    = it * 64;
    const int  u0    = super ? t0 + 64 : t0;

    __shared__ uint32_t As[2][BK4][64];
    __shared__ uint32_t Bs[2][BK4][64];

    const int tid = threadIdx.x;
    const uint32_t* hp = g_histP + (size_t)bb * NK4 * T + (size_t)ks * KHALF * T;
    const int lk = tid >> 4;           // loader: k row within chunk
    const int lq = (tid & 15) * 4;     // loader: 4-col group
    const int tx = (tid & 15) * 4;     // compute: u micro base
    const int ty = (tid >> 4) * 4;     // compute: t micro base

    unsigned int acc[4][4];
    #pragma unroll
    for (int r = 0; r < 4; r++)
        #pragma unroll
        for (int c = 0; c < 4; c++) acc[r][c] = 0u;

    // preload chunk 0
    {
        const uint32_t* rowp = hp + (size_t)lk * T;
        *(uint4*)&As[0][lk][lq] = *(const uint4*)(rowp + t0 + lq);
        *(uint4*)&Bs[0][lk][lq] = *(const uint4*)(rowp + u0 + lq);
    }
    __syncthreads();

    #pragma unroll
    for (int ch = 0; ch < NCH; ch++) {
        const int cur = ch & 1;
        if (ch + 1 < NCH) {
            const uint32_t* rowp = hp + (size_t)((ch + 1) * BK4 + lk) * T;
            uint4 a  = *(const uint4*)(rowp + t0 + lq);
            uint4 bw = *(const uint4*)(rowp + u0 + lq);
            *(uint4*)&As[cur ^ 1][lk][lq] = a;
            *(uint4*)&Bs[cur ^ 1][lk][lq] = bw;
        }
        #pragma unroll
        for (int k = 0; k < BK4; k++) {
            uint4 av = *(const uint4*)&As[cur][k][ty];
            uint4 bv = *(const uint4*)&Bs[cur][k][tx];
            unsigned int ar[4] = {av.x, av.y, av.z, av.w};
            unsigned int br[4] = {bv.x, bv.y, bv.z, bv.w};
            #pragma unroll
            for (int r = 0; r < 4; r++)
                #pragma unroll
                for (int c = 0; c < 4; c++)
                    acc[r][c] = __dp4a(ar[r], br[c], acc[r][c]);
        }
        __syncthreads();
    }

    // Epilogue: atomic-accumulate integer partial dots into the band window.
    #pragma unroll
    for (int r = 0; r < 4; r++) {
        int t = t0 + ty + r;
        #pragma unroll
        for (int c = 0; c < 4; c++) {
            int u = u0 + tx + c;
            int d = u - t;
            if (d >= -PAD && d <= PAD) {
                atomicAdd(&g_winI[(bb * T + t) * WSTRIDE + (d + PAD)], acc[r][c]);
                if (super)
                    atomicAdd(&g_winI[(bb * T + u) * WSTRIDE + (PAD - d)], acc[r][c]);
            }
        }
    }
}

// ---------------------------------------------------------------------------
// Kernel 3: out = relu(win @ fc_w + fc_b), where win[t][l] =
// g_winI[t][l] * invn[t] * invn[t+l-50] (normalization folded in here).
// R5: 256 blocks x 16 rows for ~2 blocks/SM.
// ---------------------------------------------------------------------------
__global__ void __launch_bounds__(256) fc_kernel(const float* __restrict__ fc_w,
                                                 const float* __restrict__ fc_b,
                                                 float* __restrict__ out) {
    const int tid = threadIdx.x;
    const int g0  = blockIdx.x * 16;        // global frame base
    const int t0  = g0 & (T - 1);           // within-batch index
    const int bb  = g0 >> 10;

    __shared__ float wins[16][WSTRIDE];
    for (int i = tid; i < 16 * WSTRIDE; i += 256) {
        int r = i / WSTRIDE, l = i - r * WSTRIDE;
        int u = t0 + r + l - PAD;
        float v = 0.f;
        if (l < LOOK && (unsigned)u < (unsigned)T) {
            float ivt = g_invn[bb * T + t0 + r];
            float ivu = g_invn[bb * T + u];
            v = (float)g_winI[(size_t)(g0 + r) * WSTRIDE + l] * ivt * ivu;
        }
        wins[r][l] = v;
    }
    __syncthreads();

    const int tx = (tid & 31) * 4;          // output-channel base (0..124)
    const int ty = (tid >> 5) * 2;          // t micro base (0..14)

    float4 b4 = *(const float4*)(fc_b + tx);
    float acc[2][4];
    acc[0][0] = b4.x; acc[0][1] = b4.y; acc[0][2] = b4.z; acc[0][3] = b4.w;
    acc[1][0] = b4.x; acc[1][1] = b4.y; acc[1][2] = b4.z; acc[1][3] = b4.w;

    for (int l = 0; l < LOOK; l++) {
        float4 wv = *(const float4*)(fc_w + l * ODIM + tx);
        float a0 = wins[ty + 0][l];
        float a1 = wins[ty + 1][l];
        acc[0][0] = fmaf(a0, wv.x, acc[0][0]); acc[0][1] = fmaf(a0, wv.y, acc[0][1]);
        acc[0][2] = fmaf(a0, wv.z, acc[0][2]); acc[0][3] = fmaf(a0, wv.w, acc[0][3]);
        acc[1][0] = fmaf(a1, wv.x, acc[1][0]); acc[1][1] = fmaf(a1, wv.y, acc[1][1]);
        acc[1][2] = fmaf(a1, wv.z, acc[1][2]); acc[1][3] = fmaf(a1, wv.w, acc[1][3]);
    }

    #pragma unroll
    for (int r = 0; r < 2; r++) {
        float4 o4;
        o4.x = fmaxf(acc[r][0], 0.f);
        o4.y = fmaxf(acc[r][1], 0.f);
        o4.z = fmaxf(acc[r][2], 0.f);
        o4.w = fmaxf(acc[r][3], 0.f);
        *(float4*)(out + (size_t)(g0 + ty + r) * ODIM + tx) = o4;
    }
}

// ---------------------------------------------------------------------------
extern "C" void kernel_launch(void* const* d_in, const int* in_sizes, int n_in,
                              void* d_out, int out_size) {
    const int*   frames = (const int*)d_in[0];
    const float* fc_w   = (const float*)d_in[1];
    const float* fc_b   = (const float*)d_in[2];
    float*       out    = (float*)d_out;

    hist_kernel<<<(BATCH * T) / FPB, 256>>>(frames);          // 1024 blocks
    band_kernel<<<dim3(31, BATCH, 2), 256>>>();               // 248 blocks
    fc_kernel<<<(BATCH * T) / 16, 256>>>(fc_w, fc_b, out);    // 256 blocks
}